// round 1
// baseline (speedup 1.0000x reference)
#include <cuda_runtime.h>
#include <cstdint>

// Problem constants
#define BB    4096
#define DD    128
#define HIST  50
#define TOPN  4
#define PROTO 1024
#define ITEMS 100000
#define KTOT  1152      // 384 text + 768 visual
#define K1    256       // MLP layer1 input
#define D2    64        // MLP layer2 output
#define ES    16        // samples per GEMM block

typedef unsigned long long ull;

// ---------------- scratch (__device__ globals; no allocation allowed) ----------------
__device__ float2 g_WT2[(KTOT/2)*DD];   // [k2][c] pairs of transposed [Wt|Wv]
__device__ float2 g_W1T2[(K1/2)*DD];
__device__ float2 g_W2T2[(128/2)*D2];
__device__ float  g_cb[DD];             // bt·Wt_row + bv·Wv_row
__device__ float  g_IF[BB*K1];          // inter_feat
__device__ float  g_z1[BB*DD];
__device__ float  g_z2[BB*D2];
__device__ float  g_s1[DD], g_q1[DD], g_a1[DD], g_d1[DD];
__device__ float  g_s2[D2], g_q2[D2], g_a2[D2], g_d2[D2];

__device__ __forceinline__ void ffma2(ull &acc, ull a, ull b) {
    asm("fma.rn.f32x2 %0, %1, %2, %0;" : "+l"(acc) : "l"(a), "l"(b));
}
__device__ __forceinline__ float sum2(ull v) {
    return __uint_as_float((unsigned)v) + __uint_as_float((unsigned)(v >> 32));
}

// ---------------- prep: transpose weights into k-pair float2 layout + zero stats ----
__global__ void k_prep(const float* __restrict__ Wt, const float* __restrict__ Wv,
                       const float* __restrict__ W1, const float* __restrict__ W2) {
    const int n_wt = (KTOT/2)*DD;       // 73728
    const int n_w1 = (K1/2)*DD;         // 16384
    const int n_w2 = (128/2)*D2;        // 4096
    const int n_z  = 2*DD + 2*D2;       // 384 stat slots to zero
    int total = n_wt + n_w1 + n_w2 + n_z;
    for (int i = blockIdx.x*blockDim.x + threadIdx.x; i < total; i += gridDim.x*blockDim.x) {
        if (i < n_wt) {
            int k2 = i / DD, c = i % DD;
            int ka = 2*k2, kb = ka + 1;
            float a = (ka < 384) ? Wt[c*384 + ka] : Wv[c*768 + (ka-384)];
            float b = (kb < 384) ? Wt[c*384 + kb] : Wv[c*768 + (kb-384)];
            g_WT2[i] = make_float2(a, b);
        } else if (i < n_wt + n_w1) {
            int j = i - n_wt; int k2 = j / DD, c = j % DD;
            g_W1T2[j] = make_float2(W1[c*K1 + 2*k2], W1[c*K1 + 2*k2 + 1]);
        } else if (i < n_wt + n_w1 + n_w2) {
            int j = i - n_wt - n_w1; int k2 = j / D2, c = j % D2;
            g_W2T2[j] = make_float2(W2[c*128 + 2*k2], W2[c*128 + 2*k2 + 1]);
        } else {
            int j = i - n_wt - n_w1 - n_w2;
            if (j < DD)            g_s1[j] = 0.f;
            else if (j < 2*DD)     g_q1[j-DD] = 0.f;
            else if (j < 2*DD+D2)  g_s2[j-2*DD] = 0.f;
            else                   g_q2[j-2*DD-D2] = 0.f;
        }
    }
}

// cb[c] = bt·Wt[c,:] + bv·Wv[c,:]   (one block per output column, coalesced)
__global__ void k_cb(const float* __restrict__ Wt, const float* __restrict__ Wv,
                     const float* __restrict__ bt, const float* __restrict__ bv) {
    int c = blockIdx.x, t = threadIdx.x;
    float s = 0.f;
    for (int k = t; k < 384; k += 256) s += bt[k] * Wt[c*384 + k];
    for (int k = t; k < 768; k += 256) s += bv[k] * Wv[c*768 + k];
    __shared__ float red[256];
    red[t] = s; __syncthreads();
    for (int o = 128; o; o >>= 1) { if (t < o) red[t] += red[t+o]; __syncthreads(); }
    if (t == 0) g_cb[c] = red[0];
}

// ---------------- h_u: unique-prototype mean + prompt gathers ----------------------
__global__ void k_hu(const int* __restrict__ nodes_u, const int* __restrict__ nodes_d,
                     const int* __restrict__ inter_items, const int* __restrict__ top_n,
                     const float* __restrict__ protos, const float* __restrict__ up,
                     const float* __restrict__ dp,
                     float* __restrict__ out_pu, float* __restrict__ out_hu,
                     float* __restrict__ out_pd) {
    __shared__ unsigned bm[PROTO/32];
    __shared__ float s_inv;
    int i = blockIdx.x, tid = threadIdx.x;
    if (tid < 32) bm[tid] = 0u;
    __syncthreads();
    // 50 items * 8 indices (4 text-view + 4 visual-view)
    for (int j = tid; j < HIST*8; j += 128) {
        int h = j >> 3, r = j & 7;
        int item = inter_items[i*HIST + h];
        int p = (r < 4) ? top_n[item*TOPN + r] : top_n[(item + ITEMS)*TOPN + (r - 4)];
        atomicOr(&bm[p >> 5], 1u << (p & 31));
    }
    __syncthreads();
    if (tid < 32) {
        unsigned c = __popc(bm[tid]);
        #pragma unroll
        for (int o = 16; o; o >>= 1) c += __shfl_down_sync(0xffffffffu, c, o);
        if (tid == 0) s_inv = 1.0f / (float)c;
    }
    __syncthreads();
    float acc = 0.f;
    #pragma unroll 1
    for (int w = 0; w < PROTO/32; ++w) {
        unsigned word = bm[w];
        while (word) {
            int b = __ffs(word) - 1;
            word &= (word - 1);
            acc += protos[(w*32 + b)*DD + tid];
        }
    }
    float hu = acc * s_inv;
    float pd = dp[nodes_d[i]*DD + tid];
    out_hu[i*DD + tid] = hu;
    out_pd[i*DD + tid] = pd;
    out_pu[i*DD + tid] = up[nodes_u[i]*DD + tid];
    g_IF[i*K1 + tid] = hu + pd;   // h_u_hat goes into first half of inter_feat
}

// ---------------- gathered feature GEMM: e_i_hat = (x-b)@[Wt|Wv]^T + item_prompt ----
__global__ void k_e(const int* __restrict__ nodes_v, const float* __restrict__ pre_text,
                    const float* __restrict__ pre_visual, const float* __restrict__ ip) {
    __shared__ int sv[ES];
    __shared__ __align__(16) float X[ES][64];
    int blk = blockIdx.x, tid = threadIdx.x;      // 128 threads = 1 output col each
    int c = tid;
    if (tid < ES) sv[tid] = nodes_v[blk*ES + tid];
    __syncthreads();
    ull acc[ES];
    #pragma unroll
    for (int s = 0; s < ES; ++s) acc[s] = 0ull;

    for (int ch = 0; ch < KTOT/64; ++ch) {
        int k0 = ch * 64;
        __syncthreads();
        for (int l = tid; l < ES*64; l += 128) {
            int s = l >> 6, kk = l & 63;
            int k = k0 + kk;
            X[s][kk] = (k < 384) ? pre_text[sv[s]*384 + k]
                                 : pre_visual[sv[s]*768 + (k - 384)];
        }
        __syncthreads();
        const float2* wp = &g_WT2[(k0 >> 1)*DD + c];
        #pragma unroll 4
        for (int p = 0; p < 32; ++p) {
            ull w = *(const ull*)(wp + p*DD);      // LDG.64 coalesced, L2-hot
            #pragma unroll
            for (int s = 0; s < ES; ++s) {
                ull x = *(const ull*)&X[s][2*p];   // broadcast LDS.64
                ffma2(acc[s], w, x);
            }
        }
    }
    float cbv = g_cb[c];
    #pragma unroll
    for (int s = 0; s < ES; ++s) {
        float e = sum2(acc[s]) - cbv + ip[sv[s]*DD + c];
        g_IF[(blk*ES + s)*K1 + DD + c] = e;
    }
}

// ---------------- z1 = relu(IF @ W1^T + b1), with partial BN stats -----------------
__global__ void k_z1(const float* __restrict__ b1) {
    __shared__ __align__(16) float X[ES][K1];
    int blk = blockIdx.x, c = threadIdx.x;        // 128 threads
    for (int l = c; l < ES*K1; l += 128) {
        int s = l >> 8, kk = l & 255;
        X[s][kk] = g_IF[(blk*ES + s)*K1 + kk];
    }
    __syncthreads();
    ull acc[ES];
    #pragma unroll
    for (int s = 0; s < ES; ++s) acc[s] = 0ull;
    const float2* wp = &g_W1T2[c];
    #pragma unroll 4
    for (int p = 0; p < K1/2; ++p) {
        ull w = *(const ull*)(wp + p*DD);
        #pragma unroll
        for (int s = 0; s < ES; ++s) {
            ull x = *(const ull*)&X[s][2*p];
            ffma2(acc[s], w, x);
        }
    }
    float bb = b1[c];
    float lsum = 0.f, lss = 0.f;
    #pragma unroll
    for (int s = 0; s < ES; ++s) {
        float z = sum2(acc[s]) + bb;
        z = z > 0.f ? z : 0.f;
        g_z1[(blk*ES + s)*DD + c] = z;
        lsum += z; lss += z*z;
    }
    atomicAdd(&g_s1[c], lsum);
    atomicAdd(&g_q1[c], lss);
}

__global__ void k_m1(const float* __restrict__ g1, const float* __restrict__ be1) {
    int c = threadIdx.x;  // 128
    float m = g_s1[c] * (1.0f/BB);
    float v = g_q1[c] * (1.0f/BB) - m*m;
    float r = rsqrtf(v + 1e-5f);
    float a = g1[c] * r;
    g_a1[c] = a;
    g_d1[c] = be1[c] - m*a;
}

// ---------------- z2 = relu(BN(z1) @ W2^T + b2), with partial BN stats -------------
__global__ void k_z2(const float* __restrict__ b2) {
    __shared__ __align__(16) float X[ES][128];
    int blk = blockIdx.x, c = threadIdx.x;        // 64 threads
    for (int l = c; l < ES*128; l += 64) {
        int s = l >> 7, kk = l & 127;
        X[s][kk] = g_z1[(blk*ES + s)*DD + kk] * g_a1[kk] + g_d1[kk];
    }
    __syncthreads();
    ull acc[ES];
    #pragma unroll
    for (int s = 0; s < ES; ++s) acc[s] = 0ull;
    const float2* wp = &g_W2T2[c];
    #pragma unroll 4
    for (int p = 0; p < 64; ++p) {
        ull w = *(const ull*)(wp + p*D2);
        #pragma unroll
        for (int s = 0; s < ES; ++s) {
            ull x = *(const ull*)&X[s][2*p];
            ffma2(acc[s], w, x);
        }
    }
    float bb = b2[c];
    float lsum = 0.f, lss = 0.f;
    #pragma unroll
    for (int s = 0; s < ES; ++s) {
        float z = sum2(acc[s]) + bb;
        z = z > 0.f ? z : 0.f;
        g_z2[(blk*ES + s)*D2 + c] = z;
        lsum += z; lss += z*z;
    }
    atomicAdd(&g_s2[c], lsum);
    atomicAdd(&g_q2[c], lss);
}

__global__ void k_m2(const float* __restrict__ g2, const float* __restrict__ be2) {
    int c = threadIdx.x;  // 64
    float m = g_s2[c] * (1.0f/BB);
    float v = g_q2[c] * (1.0f/BB) - m*m;
    float r = rsqrtf(v + 1e-5f);
    float a = g2[c] * r;
    g_a2[c] = a;
    g_d2[c] = be2[c] - m*a;
}

// ---------------- pred = sigmoid(BN(z2) @ Wp^T + bp) -------------------------------
__global__ void k_pred(const float* __restrict__ Wp, const float* __restrict__ bp,
                       float* __restrict__ out_pred) {
    int warp = (blockIdx.x*blockDim.x + threadIdx.x) >> 5;
    int lane = threadIdx.x & 31;
    if (warp >= BB) return;
    float t = 0.f;
    #pragma unroll
    for (int j = 0; j < 2; ++j) {
        int cidx = lane + j*32;
        float f2 = g_z2[warp*D2 + cidx] * g_a2[cidx] + g_d2[cidx];
        t += f2 * Wp[cidx];
    }
    #pragma unroll
    for (int o = 16; o; o >>= 1) t += __shfl_down_sync(0xffffffffu, t, o);
    if (lane == 0) out_pred[warp] = 1.0f / (1.0f + expf(-(t + bp[0])));
}

// ---------------- launch ------------------------------------------------------------
extern "C" void kernel_launch(void* const* d_in, const int* in_sizes, int n_in,
                              void* d_out, int out_size) {
    const int*   nodes_u     = (const int*)  d_in[0];
    const int*   nodes_v     = (const int*)  d_in[1];
    const int*   nodes_d     = (const int*)  d_in[2];
    const int*   inter_items = (const int*)  d_in[3];
    const int*   top_n       = (const int*)  d_in[4];
    const float* protos      = (const float*)d_in[5];
    const float* pre_text    = (const float*)d_in[6];
    const float* pre_visual  = (const float*)d_in[7];
    const float* Wt          = (const float*)d_in[8];
    const float* bt          = (const float*)d_in[9];
    const float* Wv          = (const float*)d_in[10];
    const float* bv          = (const float*)d_in[11];
    const float* up          = (const float*)d_in[12];
    const float* ip          = (const float*)d_in[13];
    const float* dp          = (const float*)d_in[14];
    const float* W1          = (const float*)d_in[15];
    const float* b1          = (const float*)d_in[16];
    const float* g1          = (const float*)d_in[17];
    const float* be1         = (const float*)d_in[18];
    const float* W2          = (const float*)d_in[19];
    const float* b2          = (const float*)d_in[20];
    const float* g2          = (const float*)d_in[21];
    const float* be2         = (const float*)d_in[22];
    const float* Wp          = (const float*)d_in[23];
    const float* bp          = (const float*)d_in[24];

    float* out      = (float*)d_out;
    // outputs flattened in reference return order: pred, p_u, h_u, p_d
    float* out_pred = out;
    float* out_pu   = out + BB;
    float* out_hu   = out + BB + BB*DD;
    float* out_pd   = out + BB + 2*BB*DD;

    k_prep<<<288, 256>>>(Wt, Wv, W1, W2);
    k_cb<<<DD, 256>>>(Wt, Wv, bt, bv);
    k_hu<<<BB, 128>>>(nodes_u, nodes_d, inter_items, top_n, protos, up, dp,
                      out_pu, out_hu, out_pd);
    k_e<<<BB/ES, 128>>>(nodes_v, pre_text, pre_visual, ip);
    k_z1<<<BB/ES, 128>>>(b1);
    k_m1<<<1, 128>>>(g1, be1);
    k_z2<<<BB/ES, 64>>>(b2);
    k_m2<<<1, 64>>>(g2, be2);
    k_pred<<<BB/8, 256>>>(Wp, bp, out_pred);
}

// round 2
// speedup vs baseline: 1.1840x; 1.1840x over previous
#include <cuda_runtime.h>
#include <cstdint>

// Problem constants
#define BB    4096
#define DD    128
#define HIST  50
#define TOPN  4
#define PROTO 1024
#define ITEMS 100000
#define KTOT  1152      // 384 text + 768 visual
#define K1    256       // MLP layer1 input
#define D2    64        // MLP layer2 output
#define ES    16        // samples per block (k_z1/k_z2)
#define ES2   32        // samples per block (k_e)
#define CH    32        // K-floats per k_e chunk
#define NC    (KTOT/CH) // 36 chunks

typedef unsigned long long ull;

// ---------------- scratch (__device__ globals; no allocation allowed) ----------------
__device__ float2 g_WT2[(KTOT/2)*DD];   // [k2][c] pairs of transposed [Wt|Wv]
__device__ float2 g_W1T2[(K1/2)*DD];
__device__ float2 g_W2T2[(128/2)*D2];
__device__ float  g_cb[DD];             // bt·Wt_row + bv·Wv_row
__device__ float  g_IF[BB*K1];          // inter_feat
__device__ float  g_z1[BB*DD];
__device__ float  g_z2[BB*D2];
__device__ float  g_s1[DD], g_q1[DD], g_a1[DD], g_d1[DD];
__device__ float  g_s2[D2], g_q2[D2], g_a2[D2], g_d2[D2];

__device__ __forceinline__ void ffma2(ull &acc, ull a, ull b) {
    asm("fma.rn.f32x2 %0, %1, %2, %0;" : "+l"(acc) : "l"(a), "l"(b));
}
__device__ __forceinline__ float sum2(ull v) {
    return __uint_as_float((unsigned)v) + __uint_as_float((unsigned)(v >> 32));
}
__device__ __forceinline__ void cpa16(void* dst, const void* src) {
    unsigned d = (unsigned)__cvta_generic_to_shared(dst);
    asm volatile("cp.async.cg.shared.global [%0], [%1], 16;" :: "r"(d), "l"(src));
}
__device__ __forceinline__ void cpa_commit() { asm volatile("cp.async.commit_group;"); }
__device__ __forceinline__ void cpa_wait1() { asm volatile("cp.async.wait_group 1;"); }
__device__ __forceinline__ void cpa_wait0() { asm volatile("cp.async.wait_group 0;"); }

// ---------------- prep: transpose weights into k-pair float2 layout + zero stats ----
__global__ void k_prep(const float* __restrict__ Wt, const float* __restrict__ Wv,
                       const float* __restrict__ W1, const float* __restrict__ W2) {
    const int n_wt = (KTOT/2)*DD;       // 73728
    const int n_w1 = (K1/2)*DD;         // 16384
    const int n_w2 = (128/2)*D2;        // 4096
    const int n_z  = 2*DD + 2*D2;       // 384 stat slots to zero
    int total = n_wt + n_w1 + n_w2 + n_z;
    for (int i = blockIdx.x*blockDim.x + threadIdx.x; i < total; i += gridDim.x*blockDim.x) {
        if (i < n_wt) {
            int k2 = i / DD, c = i % DD;
            int ka = 2*k2, kb = ka + 1;
            float a = (ka < 384) ? Wt[c*384 + ka] : Wv[c*768 + (ka-384)];
            float b = (kb < 384) ? Wt[c*384 + kb] : Wv[c*768 + (kb-384)];
            g_WT2[i] = make_float2(a, b);
        } else if (i < n_wt + n_w1) {
            int j = i - n_wt; int k2 = j / DD, c = j % DD;
            g_W1T2[j] = make_float2(W1[c*K1 + 2*k2], W1[c*K1 + 2*k2 + 1]);
        } else if (i < n_wt + n_w1 + n_w2) {
            int j = i - n_wt - n_w1; int k2 = j / D2, c = j % D2;
            g_W2T2[j] = make_float2(W2[c*128 + 2*k2], W2[c*128 + 2*k2 + 1]);
        } else {
            int j = i - n_wt - n_w1 - n_w2;
            if (j < DD)            g_s1[j] = 0.f;
            else if (j < 2*DD)     g_q1[j-DD] = 0.f;
            else if (j < 2*DD+D2)  g_s2[j-2*DD] = 0.f;
            else                   g_q2[j-2*DD-D2] = 0.f;
        }
    }
}

// cb[c] = bt·Wt[c,:] + bv·Wv[c,:]
__global__ void k_cb(const float* __restrict__ Wt, const float* __restrict__ Wv,
                     const float* __restrict__ bt, const float* __restrict__ bv) {
    int c = blockIdx.x, t = threadIdx.x;
    float s = 0.f;
    for (int k = t; k < 384; k += 256) s += bt[k] * Wt[c*384 + k];
    for (int k = t; k < 768; k += 256) s += bv[k] * Wv[c*768 + k];
    __shared__ float red[256];
    red[t] = s; __syncthreads();
    for (int o = 128; o; o >>= 1) { if (t < o) red[t] += red[t+o]; __syncthreads(); }
    if (t == 0) g_cb[c] = red[0];
}

// ---------------- h_u: unique-prototype mean + prompt gathers ----------------------
__global__ void k_hu(const int* __restrict__ nodes_u, const int* __restrict__ nodes_d,
                     const int* __restrict__ inter_items, const int* __restrict__ top_n,
                     const float* __restrict__ protos, const float* __restrict__ up,
                     const float* __restrict__ dp,
                     float* __restrict__ out_pu, float* __restrict__ out_hu,
                     float* __restrict__ out_pd) {
    __shared__ unsigned bm[PROTO/32];
    __shared__ float s_inv;
    int i = blockIdx.x, tid = threadIdx.x;
    if (tid < 32) bm[tid] = 0u;
    __syncthreads();
    for (int j = tid; j < HIST*8; j += 128) {
        int h = j >> 3, r = j & 7;
        int item = inter_items[i*HIST + h];
        int p = (r < 4) ? top_n[item*TOPN + r] : top_n[(item + ITEMS)*TOPN + (r - 4)];
        atomicOr(&bm[p >> 5], 1u << (p & 31));
    }
    __syncthreads();
    if (tid < 32) {
        unsigned c = __popc(bm[tid]);
        #pragma unroll
        for (int o = 16; o; o >>= 1) c += __shfl_down_sync(0xffffffffu, c, o);
        if (tid == 0) s_inv = 1.0f / (float)c;
    }
    __syncthreads();
    float acc = 0.f;
    #pragma unroll 1
    for (int w = 0; w < PROTO/32; ++w) {
        unsigned word = bm[w];
        while (word) {
            int b = __ffs(word) - 1;
            word &= (word - 1);
            acc += protos[(w*32 + b)*DD + tid];
        }
    }
    float hu = acc * s_inv;
    float pd = dp[nodes_d[i]*DD + tid];
    out_hu[i*DD + tid] = hu;
    out_pd[i*DD + tid] = pd;
    out_pu[i*DD + tid] = up[nodes_u[i]*DD + tid];
    g_IF[i*K1 + tid] = hu + pd;
}

// ---------------- gathered feature GEMM (smem-staged, cp.async double-buffered) ----
// e_i_hat = (x-b)@[Wt|Wv]^T + item_prompt ; 256 threads, 32 samples/block, grid=128
__global__ void __launch_bounds__(256) k_e(
        const int* __restrict__ nodes_v, const float* __restrict__ pre_text,
        const float* __restrict__ pre_visual, const float* __restrict__ ip) {
    __shared__ int svs[ES2];
    __shared__ __align__(16) float2 Wb[2][(CH/2)*DD];  // 16KB each
    __shared__ __align__(16) float  Xb[2][ES2][CH];    // 4KB each
    int blk = blockIdx.x, tid = threadIdx.x;
    int c = tid & 127, h = tid >> 7;                   // column, sample-half
    if (tid < ES2) svs[tid] = nodes_v[blk*ES2 + tid];
    __syncthreads();
    int xs = tid >> 3, xj = tid & 7;                   // X-stage: sample, 16B chunk
    int xrow = svs[xs];

    auto stage = [&](int ch, int b) {
        int k0 = ch * CH;
        // W chunk: 16KB contiguous, 64B per thread
        const float2* wsrc = &g_WT2[(k0 >> 1)*DD];
        #pragma unroll
        for (int i = 0; i < 4; ++i)
            cpa16(&Wb[b][tid*8 + i*2], &wsrc[tid*8 + i*2]);
        // X chunk: 32 samples x 128B, 16B per thread
        const float* src = (k0 < 384) ? (pre_text + (size_t)xrow*384 + k0)
                                      : (pre_visual + (size_t)xrow*768 + (k0 - 384));
        cpa16(&Xb[b][xs][xj*4], src + xj*4);
        cpa_commit();
    };

    ull acc[16];
    #pragma unroll
    for (int s = 0; s < 16; ++s) acc[s] = 0ull;

    stage(0, 0);
    for (int ch = 0; ch < NC; ++ch) {
        int b = ch & 1;
        bool more = (ch + 1 < NC);
        if (more) stage(ch + 1, 1 - b);
        if (more) cpa_wait1(); else cpa_wait0();
        __syncthreads();
        const float2* W = Wb[b];
        #pragma unroll
        for (int p = 0; p < CH/2; p += 2) {
            ull w0 = *(const ull*)&W[p*DD + c];
            ull w1 = *(const ull*)&W[(p+1)*DD + c];
            #pragma unroll
            for (int s = 0; s < 16; ++s) {
                ulonglong2 x = *(const ulonglong2*)&Xb[b][h*16 + s][2*p];
                ffma2(acc[s], w0, x.x);
                ffma2(acc[s], w1, x.y);
            }
        }
        __syncthreads();
    }
    float cbv = g_cb[c];
    #pragma unroll
    for (int s = 0; s < 16; ++s) {
        int smp = h*16 + s;
        float e = sum2(acc[s]) - cbv + ip[(size_t)svs[smp]*DD + c];
        g_IF[(blk*ES2 + smp)*K1 + DD + c] = e;
    }
}

// ---------------- z1 = relu(IF @ W1^T + b1), with partial BN stats -----------------
__global__ void k_z1(const float* __restrict__ b1) {
    __shared__ __align__(16) float X[ES][K1];
    int blk = blockIdx.x, c = threadIdx.x;        // 128 threads
    for (int l = c; l < ES*K1; l += 128) {
        int s = l >> 8, kk = l & 255;
        X[s][kk] = g_IF[(blk*ES + s)*K1 + kk];
    }
    __syncthreads();
    ull acc[ES];
    #pragma unroll
    for (int s = 0; s < ES; ++s) acc[s] = 0ull;
    const float2* wp = &g_W1T2[c];
    #pragma unroll 8
    for (int p = 0; p < K1/2; ++p) {
        ull w = *(const ull*)(wp + p*DD);
        #pragma unroll
        for (int s = 0; s < ES; ++s) {
            ull x = *(const ull*)&X[s][2*p];
            ffma2(acc[s], w, x);
        }
    }
    float bb = b1[c];
    float lsum = 0.f, lss = 0.f;
    #pragma unroll
    for (int s = 0; s < ES; ++s) {
        float z = sum2(acc[s]) + bb;
        z = z > 0.f ? z : 0.f;
        g_z1[(blk*ES + s)*DD + c] = z;
        lsum += z; lss += z*z;
    }
    atomicAdd(&g_s1[c], lsum);
    atomicAdd(&g_q1[c], lss);
}

__global__ void k_m1(const float* __restrict__ g1, const float* __restrict__ be1) {
    int c = threadIdx.x;  // 128
    float m = g_s1[c] * (1.0f/BB);
    float v = g_q1[c] * (1.0f/BB) - m*m;
    float r = rsqrtf(v + 1e-5f);
    float a = g1[c] * r;
    g_a1[c] = a;
    g_d1[c] = be1[c] - m*a;
}

// ---------------- z2 = relu(BN(z1) @ W2^T + b2), with partial BN stats -------------
__global__ void k_z2(const float* __restrict__ b2) {
    __shared__ __align__(16) float X[ES][128];
    int blk = blockIdx.x, c = threadIdx.x;        // 64 threads
    for (int l = c; l < ES*128; l += 64) {
        int s = l >> 7, kk = l & 127;
        X[s][kk] = g_z1[(blk*ES + s)*DD + kk] * g_a1[kk] + g_d1[kk];
    }
    __syncthreads();
    ull acc[ES];
    #pragma unroll
    for (int s = 0; s < ES; ++s) acc[s] = 0ull;
    const float2* wp = &g_W2T2[c];
    #pragma unroll 8
    for (int p = 0; p < 64; ++p) {
        ull w = *(const ull*)(wp + p*D2);
        #pragma unroll
        for (int s = 0; s < ES; ++s) {
            ull x = *(const ull*)&X[s][2*p];
            ffma2(acc[s], w, x);
        }
    }
    float bb = b2[c];
    float lsum = 0.f, lss = 0.f;
    #pragma unroll
    for (int s = 0; s < ES; ++s) {
        float z = sum2(acc[s]) + bb;
        z = z > 0.f ? z : 0.f;
        g_z2[(blk*ES + s)*D2 + c] = z;
        lsum += z; lss += z*z;
    }
    atomicAdd(&g_s2[c], lsum);
    atomicAdd(&g_q2[c], lss);
}

__global__ void k_m2(const float* __restrict__ g2, const float* __restrict__ be2) {
    int c = threadIdx.x;  // 64
    float m = g_s2[c] * (1.0f/BB);
    float v = g_q2[c] * (1.0f/BB) - m*m;
    float r = rsqrtf(v + 1e-5f);
    float a = g2[c] * r;
    g_a2[c] = a;
    g_d2[c] = be2[c] - m*a;
}

// ---------------- pred = sigmoid(BN(z2) @ Wp^T + bp) -------------------------------
__global__ void k_pred(const float* __restrict__ Wp, const float* __restrict__ bp,
                       float* __restrict__ out_pred) {
    int warp = (blockIdx.x*blockDim.x + threadIdx.x) >> 5;
    int lane = threadIdx.x & 31;
    if (warp >= BB) return;
    float t = 0.f;
    #pragma unroll
    for (int j = 0; j < 2; ++j) {
        int cidx = lane + j*32;
        float f2 = g_z2[warp*D2 + cidx] * g_a2[cidx] + g_d2[cidx];
        t += f2 * Wp[cidx];
    }
    #pragma unroll
    for (int o = 16; o; o >>= 1) t += __shfl_down_sync(0xffffffffu, t, o);
    if (lane == 0) out_pred[warp] = 1.0f / (1.0f + expf(-(t + bp[0])));
}

// ---------------- launch ------------------------------------------------------------
extern "C" void kernel_launch(void* const* d_in, const int* in_sizes, int n_in,
                              void* d_out, int out_size) {
    const int*   nodes_u     = (const int*)  d_in[0];
    const int*   nodes_v     = (const int*)  d_in[1];
    const int*   nodes_d     = (const int*)  d_in[2];
    const int*   inter_items = (const int*)  d_in[3];
    const int*   top_n       = (const int*)  d_in[4];
    const float* protos      = (const float*)d_in[5];
    const float* pre_text    = (const float*)d_in[6];
    const float* pre_visual  = (const float*)d_in[7];
    const float* Wt          = (const float*)d_in[8];
    const float* bt          = (const float*)d_in[9];
    const float* Wv          = (const float*)d_in[10];
    const float* bv          = (const float*)d_in[11];
    const float* up          = (const float*)d_in[12];
    const float* ip          = (const float*)d_in[13];
    const float* dp          = (const float*)d_in[14];
    const float* W1          = (const float*)d_in[15];
    const float* b1          = (const float*)d_in[16];
    const float* g1          = (const float*)d_in[17];
    const float* be1         = (const float*)d_in[18];
    const float* W2          = (const float*)d_in[19];
    const float* b2          = (const float*)d_in[20];
    const float* g2          = (const float*)d_in[21];
    const float* be2         = (const float*)d_in[22];
    const float* Wp          = (const float*)d_in[23];
    const float* bp          = (const float*)d_in[24];

    float* out      = (float*)d_out;
    float* out_pred = out;
    float* out_pu   = out + BB;
    float* out_hu   = out + BB + BB*DD;
    float* out_pd   = out + BB + 2*BB*DD;

    k_prep<<<288, 256>>>(Wt, Wv, W1, W2);
    k_cb<<<DD, 256>>>(Wt, Wv, bt, bv);
    k_hu<<<BB, 128>>>(nodes_u, nodes_d, inter_items, top_n, protos, up, dp,
                      out_pu, out_hu, out_pd);
    k_e<<<BB/ES2, 256>>>(nodes_v, pre_text, pre_visual, ip);
    k_z1<<<BB/ES, 128>>>(b1);
    k_m1<<<1, 128>>>(g1, be1);
    k_z2<<<BB/ES, 64>>>(b2);
    k_m2<<<1, 64>>>(g2, be2);
    k_pred<<<BB/8, 256>>>(Wp, bp, out_pred);
}

// round 3
// speedup vs baseline: 1.2082x; 1.0205x over previous
#include <cuda_runtime.h>
#include <cstdint>

// Problem constants
#define BB    4096
#define DD    128
#define HIST  50
#define TOPN  4
#define PROTO 1024
#define ITEMS 100000
#define KTOT  1152      // 384 text + 768 visual
#define K1    256       // MLP layer1 input
#define D2    64        // MLP layer2 output
#define ESG   16        // samples per GEMM block
#define CH    32        // K-floats per chunk

typedef unsigned long long ull;

// ---------------- scratch (__device__ globals; no allocation allowed) ----------------
__device__ float2 g_WT2[(KTOT/2)*DD];   // [k2][c] pairs of transposed [Wt|Wv]
__device__ float2 g_PT2[(PROTO/2)*DD];  // [k2][c] pairs of transposed prototypes
__device__ float2 g_W1T2[(K1/2)*DD];
__device__ float2 g_W2T2[(DD/2)*D2];
__device__ float  g_cb[DD];             // bt·Wt_row + bv·Wv_row
__device__ float  g_mask[BB*PROTO];     // 0/1 presence mask (16MB)
__device__ float  g_cinv[BB];           // 1/unique-count
__device__ float  g_IF[BB*K1];          // inter_feat
__device__ float  g_z1[BB*DD];
__device__ float  g_z2[BB*D2];
__device__ float  g_s1[DD], g_q1[DD], g_a1[DD], g_d1[DD];
__device__ float  g_s2[D2], g_q2[D2], g_a2[D2], g_d2[D2];

__device__ __forceinline__ void ffma2(ull &acc, ull a, ull b) {
    asm("fma.rn.f32x2 %0, %1, %2, %0;" : "+l"(acc) : "l"(a), "l"(b));
}
__device__ __forceinline__ float sum2(ull v) {
    return __uint_as_float((unsigned)v) + __uint_as_float((unsigned)(v >> 32));
}
__device__ __forceinline__ void cpa16(void* dst, const void* src) {
    unsigned d = (unsigned)__cvta_generic_to_shared(dst);
    asm volatile("cp.async.cg.shared.global [%0], [%1], 16;" :: "r"(d), "l"(src));
}
__device__ __forceinline__ void cpa_commit() { asm volatile("cp.async.commit_group;"); }
__device__ __forceinline__ void cpa_wait1() { asm volatile("cp.async.wait_group 1;"); }
__device__ __forceinline__ void cpa_wait0() { asm volatile("cp.async.wait_group 0;"); }

// ---------------- prep: transpose weights into k-pair float2 layout + zero stats ----
__global__ void k_prep(const float* __restrict__ Wt, const float* __restrict__ Wv,
                       const float* __restrict__ W1, const float* __restrict__ W2,
                       const float* __restrict__ protos) {
    const int n_wt = (KTOT/2)*DD;       // 73728
    const int n_pt = (PROTO/2)*DD;      // 65536
    const int n_w1 = (K1/2)*DD;         // 16384
    const int n_w2 = (DD/2)*D2;         // 4096
    const int n_z  = 2*DD + 2*D2;
    int total = n_wt + n_pt + n_w1 + n_w2 + n_z;
    for (int i = blockIdx.x*blockDim.x + threadIdx.x; i < total; i += gridDim.x*blockDim.x) {
        if (i < n_wt) {
            int k2 = i / DD, c = i % DD;
            int ka = 2*k2, kb = ka + 1;
            float a = (ka < 384) ? Wt[c*384 + ka] : Wv[c*768 + (ka-384)];
            float b = (kb < 384) ? Wt[c*384 + kb] : Wv[c*768 + (kb-384)];
            g_WT2[i] = make_float2(a, b);
        } else if (i < n_wt + n_pt) {
            int j = i - n_wt; int k2 = j / DD, c = j % DD;
            g_PT2[j] = make_float2(protos[(2*k2)*DD + c], protos[(2*k2+1)*DD + c]);
        } else if (i < n_wt + n_pt + n_w1) {
            int j = i - n_wt - n_pt; int k2 = j / DD, c = j % DD;
            g_W1T2[j] = make_float2(W1[c*K1 + 2*k2], W1[c*K1 + 2*k2 + 1]);
        } else if (i < n_wt + n_pt + n_w1 + n_w2) {
            int j = i - n_wt - n_pt - n_w1; int k2 = j / D2, c = j % D2;
            g_W2T2[j] = make_float2(W2[c*DD + 2*k2], W2[c*DD + 2*k2 + 1]);
        } else {
            int j = i - n_wt - n_pt - n_w1 - n_w2;
            if (j < DD)            g_s1[j] = 0.f;
            else if (j < 2*DD)     g_q1[j-DD] = 0.f;
            else if (j < 2*DD+D2)  g_s2[j-2*DD] = 0.f;
            else                   g_q2[j-2*DD-D2] = 0.f;
        }
    }
}

// cb[c] = bt·Wt[c,:] + bv·Wv[c,:]
__global__ void k_cb(const float* __restrict__ Wt, const float* __restrict__ Wv,
                     const float* __restrict__ bt, const float* __restrict__ bv) {
    int c = blockIdx.x, t = threadIdx.x;
    float s = 0.f;
    for (int k = t; k < 384; k += 256) s += bt[k] * Wt[c*384 + k];
    for (int k = t; k < 768; k += 256) s += bv[k] * Wv[c*768 + k];
    __shared__ float red[256];
    red[t] = s; __syncthreads();
    for (int o = 128; o; o >>= 1) { if (t < o) red[t] += red[t+o]; __syncthreads(); }
    if (t == 0) g_cb[c] = red[0];
}

// ---------------- mask build: bitmask -> dense float mask + counts + prompt gathers --
__global__ void k_mask(const int* __restrict__ nodes_u, const int* __restrict__ nodes_d,
                       const int* __restrict__ inter_items, const int* __restrict__ top_n,
                       const float* __restrict__ up, const float* __restrict__ dp,
                       float* __restrict__ out_pu, float* __restrict__ out_pd) {
    __shared__ unsigned bm[PROTO/32];
    int i = blockIdx.x, tid = threadIdx.x;
    if (tid < 32) bm[tid] = 0u;
    __syncthreads();
    for (int j = tid; j < HIST*8; j += 128) {
        int h = j >> 3, r = j & 7;
        int item = inter_items[i*HIST + h];
        int p = (r < 4) ? top_n[item*TOPN + r] : top_n[(item + ITEMS)*TOPN + (r - 4)];
        atomicOr(&bm[p >> 5], 1u << (p & 31));
    }
    __syncthreads();
    if (tid < 32) {
        unsigned c = __popc(bm[tid]);
        #pragma unroll
        for (int o = 16; o; o >>= 1) c += __shfl_down_sync(0xffffffffu, c, o);
        if (tid == 0) g_cinv[i] = 1.0f / (float)c;
    }
    // dense 0/1 float write: 8 floats per thread (two st.128)
    unsigned w = bm[tid >> 2];
    int sh = (tid & 3) * 8;
    float4 a, b;
    a.x = (w >> (sh+0)) & 1 ? 1.f : 0.f;  a.y = (w >> (sh+1)) & 1 ? 1.f : 0.f;
    a.z = (w >> (sh+2)) & 1 ? 1.f : 0.f;  a.w = (w >> (sh+3)) & 1 ? 1.f : 0.f;
    b.x = (w >> (sh+4)) & 1 ? 1.f : 0.f;  b.y = (w >> (sh+5)) & 1 ? 1.f : 0.f;
    b.z = (w >> (sh+6)) & 1 ? 1.f : 0.f;  b.w = (w >> (sh+7)) & 1 ? 1.f : 0.f;
    float4* mrow = (float4*)&g_mask[(size_t)i*PROTO + tid*8];
    mrow[0] = a; mrow[1] = b;
    out_pu[i*DD + tid] = up[nodes_u[i]*DD + tid];
    out_pd[i*DD + tid] = dp[nodes_d[i]*DD + tid];
}

// ===================================================================================
// Shared GEMM tile geometry (256 threads): thread = 2 cols x 4 samples.
//   warp w (0..7) covers col-groups w*8..w*8+7 ; lane = sg*8 + cgl
//   cg = w*8+cgl in [0,64): cols 2*cg, 2*cg+1 ; sg in [0,4): samples sg*4..sg*4+3
// W smem chunk: [16 k2][64 cg] x 16B = 16KB (contiguous copy of the k-pair layout)
// X smem chunk: [16 samples][32 k floats] = 2KB
// ===================================================================================

// ---------------- h_u GEMM: h_u = (mask @ protos) * cinv ; IF[:,0:128] = h_u + p_d --
__global__ void __launch_bounds__(256) k_hu(const int* __restrict__ nodes_d,
                                            const float* __restrict__ dp,
                                            float* __restrict__ out_hu) {
    __shared__ __align__(16) ulonglong2 Wb[2][16*64];
    __shared__ __align__(16) float Xb[2][ESG][CH];
    int blk = blockIdx.x, tid = threadIdx.x;
    int w = tid >> 5, lane = tid & 31;
    int sg = lane >> 3, cgl = lane & 7, cg = w*8 + cgl;
    int c0 = cg*2;
    int xs = tid >> 3, xj = tid & 7;   // X staging role (tid<128)

    auto stage = [&](int ch, int b) {
        const float4* wsrc = (const float4*)(g_PT2 + (ch*(CH/2))*DD);
        const float4* wdst = (const float4*)Wb[b];
        #pragma unroll
        for (int i = 0; i < 4; ++i)
            cpa16((void*)(wdst + tid*4 + i), wsrc + tid*4 + i);
        if (tid < 128)
            cpa16(&Xb[b][xs][xj*4], &g_mask[(size_t)(blk*ESG + xs)*PROTO + ch*CH + xj*4]);
        cpa_commit();
    };

    ull acc[4][2];
    #pragma unroll
    for (int i = 0; i < 4; ++i) { acc[i][0] = 0ull; acc[i][1] = 0ull; }

    const int NCH = PROTO/CH;   // 32
    stage(0, 0);
    for (int ch = 0; ch < NCH; ++ch) {
        int b = ch & 1;
        bool more = (ch + 1 < NCH);
        if (more) stage(ch + 1, 1 - b);
        if (more) cpa_wait1(); else cpa_wait0();
        __syncthreads();
        #pragma unroll
        for (int p2 = 0; p2 < 8; ++p2) {
            ulonglong2 w0 = Wb[b][(2*p2)*64 + cg];
            ulonglong2 w1 = Wb[b][(2*p2+1)*64 + cg];
            #pragma unroll
            for (int i = 0; i < 4; ++i) {
                ulonglong2 x = *(const ulonglong2*)&Xb[b][sg*4 + i][4*p2];
                ffma2(acc[i][0], w0.x, x.x);
                ffma2(acc[i][1], w0.y, x.x);
                ffma2(acc[i][0], w1.x, x.y);
                ffma2(acc[i][1], w1.y, x.y);
            }
        }
        __syncthreads();
    }
    #pragma unroll
    for (int i = 0; i < 4; ++i) {
        int s = blk*ESG + sg*4 + i;
        float inv = g_cinv[s];
        int nd = nodes_d[s];
        float h0 = sum2(acc[i][0]) * inv;
        float h1 = sum2(acc[i][1]) * inv;
        *(float2*)&out_hu[s*DD + c0] = make_float2(h0, h1);
        float2 pd = *(const float2*)&dp[nd*DD + c0];
        *(float2*)&g_IF[s*K1 + c0] = make_float2(h0 + pd.x, h1 + pd.y);
    }
}

// ---------------- e_i_hat GEMM: (x-b)@[Wt|Wv]^T + item_prompt -> IF[:,128:256] ------
__global__ void __launch_bounds__(256) k_e(
        const int* __restrict__ nodes_v, const float* __restrict__ pre_text,
        const float* __restrict__ pre_visual, const float* __restrict__ ip) {
    __shared__ int svs[ESG];
    __shared__ __align__(16) ulonglong2 Wb[2][16*64];
    __shared__ __align__(16) float Xb[2][ESG][CH];
    int blk = blockIdx.x, tid = threadIdx.x;
    int w = tid >> 5, lane = tid & 31;
    int sg = lane >> 3, cgl = lane & 7, cg = w*8 + cgl;
    int c0 = cg*2;
    if (tid < ESG) svs[tid] = nodes_v[blk*ESG + tid];
    __syncthreads();
    int xs = tid >> 3, xj = tid & 7;
    int xrow = (tid < 128) ? svs[xs] : 0;

    auto stage = [&](int ch, int b) {
        int k0 = ch * CH;
        const float4* wsrc = (const float4*)(g_WT2 + (k0 >> 1)*DD);
        const float4* wdst = (const float4*)Wb[b];
        #pragma unroll
        for (int i = 0; i < 4; ++i)
            cpa16((void*)(wdst + tid*4 + i), wsrc + tid*4 + i);
        if (tid < 128) {
            const float* src = (k0 < 384) ? (pre_text + (size_t)xrow*384 + k0)
                                          : (pre_visual + (size_t)xrow*768 + (k0 - 384));
            cpa16(&Xb[b][xs][xj*4], src + xj*4);
        }
        cpa_commit();
    };

    ull acc[4][2];
    #pragma unroll
    for (int i = 0; i < 4; ++i) { acc[i][0] = 0ull; acc[i][1] = 0ull; }

    const int NCH = KTOT/CH;    // 36
    stage(0, 0);
    for (int ch = 0; ch < NCH; ++ch) {
        int b = ch & 1;
        bool more = (ch + 1 < NCH);
        if (more) stage(ch + 1, 1 - b);
        if (more) cpa_wait1(); else cpa_wait0();
        __syncthreads();
        #pragma unroll
        for (int p2 = 0; p2 < 8; ++p2) {
            ulonglong2 w0 = Wb[b][(2*p2)*64 + cg];
            ulonglong2 w1 = Wb[b][(2*p2+1)*64 + cg];
            #pragma unroll
            for (int i = 0; i < 4; ++i) {
                ulonglong2 x = *(const ulonglong2*)&Xb[b][sg*4 + i][4*p2];
                ffma2(acc[i][0], w0.x, x.x);
                ffma2(acc[i][1], w0.y, x.x);
                ffma2(acc[i][0], w1.x, x.y);
                ffma2(acc[i][1], w1.y, x.y);
            }
        }
        __syncthreads();
    }
    float2 cbv = *(const float2*)&g_cb[c0];
    #pragma unroll
    for (int i = 0; i < 4; ++i) {
        int sl = sg*4 + i;
        int s = blk*ESG + sl;
        float2 ipv = *(const float2*)&ip[(size_t)svs[sl]*DD + c0];
        float e0 = sum2(acc[i][0]) - cbv.x + ipv.x;
        float e1 = sum2(acc[i][1]) - cbv.y + ipv.y;
        *(float2*)&g_IF[s*K1 + DD + c0] = make_float2(e0, e1);
    }
}

// ---------------- z1 = relu(IF @ W1^T + b1) + partial BN stats ---------------------
__global__ void __launch_bounds__(256) k_z1(const float* __restrict__ b1) {
    __shared__ __align__(16) ulonglong2 Wb[2][16*64];
    __shared__ __align__(16) float Xb[2][ESG][CH];
    int blk = blockIdx.x, tid = threadIdx.x;
    int w = tid >> 5, lane = tid & 31;
    int sg = lane >> 3, cgl = lane & 7, cg = w*8 + cgl;
    int c0 = cg*2;
    int xs = tid >> 3, xj = tid & 7;

    auto stage = [&](int ch, int b) {
        const float4* wsrc = (const float4*)(g_W1T2 + (ch*(CH/2))*DD);
        const float4* wdst = (const float4*)Wb[b];
        #pragma unroll
        for (int i = 0; i < 4; ++i)
            cpa16((void*)(wdst + tid*4 + i), wsrc + tid*4 + i);
        if (tid < 128)
            cpa16(&Xb[b][xs][xj*4], &g_IF[(blk*ESG + xs)*K1 + ch*CH + xj*4]);
        cpa_commit();
    };

    ull acc[4][2];
    #pragma unroll
    for (int i = 0; i < 4; ++i) { acc[i][0] = 0ull; acc[i][1] = 0ull; }

    const int NCH = K1/CH;  // 8
    stage(0, 0);
    for (int ch = 0; ch < NCH; ++ch) {
        int b = ch & 1;
        bool more = (ch + 1 < NCH);
        if (more) stage(ch + 1, 1 - b);
        if (more) cpa_wait1(); else cpa_wait0();
        __syncthreads();
        #pragma unroll
        for (int p2 = 0; p2 < 8; ++p2) {
            ulonglong2 w0 = Wb[b][(2*p2)*64 + cg];
            ulonglong2 w1 = Wb[b][(2*p2+1)*64 + cg];
            #pragma unroll
            for (int i = 0; i < 4; ++i) {
                ulonglong2 x = *(const ulonglong2*)&Xb[b][sg*4 + i][4*p2];
                ffma2(acc[i][0], w0.x, x.x);
                ffma2(acc[i][1], w0.y, x.x);
                ffma2(acc[i][0], w1.x, x.y);
                ffma2(acc[i][1], w1.y, x.y);
            }
        }
        __syncthreads();
    }
    float2 bb = *(const float2*)&b1[c0];
    float s0 = 0.f, s1 = 0.f, q0 = 0.f, q1 = 0.f;
    #pragma unroll
    for (int i = 0; i < 4; ++i) {
        int s = blk*ESG + sg*4 + i;
        float z0 = sum2(acc[i][0]) + bb.x;  z0 = z0 > 0.f ? z0 : 0.f;
        float z1v = sum2(acc[i][1]) + bb.y; z1v = z1v > 0.f ? z1v : 0.f;
        *(float2*)&g_z1[s*DD + c0] = make_float2(z0, z1v);
        s0 += z0; s1 += z1v; q0 += z0*z0; q1 += z1v*z1v;
    }
    // reduce across sample-groups (lane bits 3,4), then one atomic per col
    #pragma unroll
    for (int o = 8; o <= 16; o <<= 1) {
        s0 += __shfl_xor_sync(0xffffffffu, s0, o);
        s1 += __shfl_xor_sync(0xffffffffu, s1, o);
        q0 += __shfl_xor_sync(0xffffffffu, q0, o);
        q1 += __shfl_xor_sync(0xffffffffu, q1, o);
    }
    if (sg == 0) {
        atomicAdd(&g_s1[c0], s0);   atomicAdd(&g_s1[c0+1], s1);
        atomicAdd(&g_q1[c0], q0);   atomicAdd(&g_q1[c0+1], q1);
    }
}

__global__ void k_m1(const float* __restrict__ g1, const float* __restrict__ be1) {
    int c = threadIdx.x;  // 128
    float m = g_s1[c] * (1.0f/BB);
    float v = g_q1[c] * (1.0f/BB) - m*m;
    float r = rsqrtf(v + 1e-5f);
    float a = g1[c] * r;
    g_a1[c] = a;
    g_d1[c] = be1[c] - m*a;
}

// ---------------- z2 = relu(BN(z1) @ W2^T + b2) + partial BN stats -----------------
// 128 threads: c = tid&63 (col), h = tid>>6 (sample half of 8). W2 fully in smem.
__global__ void __launch_bounds__(128) k_z2(const float* __restrict__ b2) {
    __shared__ __align__(16) float2 W2s[(DD/2)*D2];  // 32KB
    __shared__ __align__(16) float X[ESG][DD];       // 8KB
    __shared__ float A1[DD], D1[DD];
    int blk = blockIdx.x, tid = threadIdx.x;
    int c = tid & 63, h = tid >> 6;
    if (tid < DD) { A1[tid] = g_a1[tid]; D1[tid] = g_d1[tid]; }
    // stage W2 (32KB) via cp.async
    {
        const float4* src = (const float4*)g_W2T2;
        float4* dst = (float4*)W2s;
        #pragma unroll
        for (int i = 0; i < 16; ++i)
            cpa16(dst + tid + i*128, src + tid + i*128);
        cpa_commit();
    }
    __syncthreads();
    for (int l = tid; l < ESG*DD; l += 128) {
        int s = l >> 7, kk = l & 127;
        X[s][kk] = g_z1[(blk*ESG + s)*DD + kk] * A1[kk] + D1[kk];
    }
    cpa_wait0();
    __syncthreads();
    ull acc[8];
    #pragma unroll
    for (int i = 0; i < 8; ++i) acc[i] = 0ull;
    #pragma unroll 8
    for (int p = 0; p < DD/2; ++p) {
        ull wv = *(const ull*)&W2s[p*D2 + c];
        #pragma unroll
        for (int i = 0; i < 8; ++i) {
            ull x = *(const ull*)&X[h*8 + i][2*p];
            ffma2(acc[i], wv, x);
        }
    }
    float bb = b2[c];
    float lsum = 0.f, lss = 0.f;
    #pragma unroll
    for (int i = 0; i < 8; ++i) {
        float z = sum2(acc[i]) + bb;
        z = z > 0.f ? z : 0.f;
        g_z2[(blk*ESG + h*8 + i)*D2 + c] = z;
        lsum += z; lss += z*z;
    }
    atomicAdd(&g_s2[c], lsum);
    atomicAdd(&g_q2[c], lss);
}

__global__ void k_m2(const float* __restrict__ g2, const float* __restrict__ be2) {
    int c = threadIdx.x;  // 64
    float m = g_s2[c] * (1.0f/BB);
    float v = g_q2[c] * (1.0f/BB) - m*m;
    float r = rsqrtf(v + 1e-5f);
    float a = g2[c] * r;
    g_a2[c] = a;
    g_d2[c] = be2[c] - m*a;
}

// ---------------- pred = sigmoid(BN(z2) @ Wp^T + bp) -------------------------------
__global__ void k_pred(const float* __restrict__ Wp, const float* __restrict__ bp,
                       float* __restrict__ out_pred) {
    int warp = (blockIdx.x*blockDim.x + threadIdx.x) >> 5;
    int lane = threadIdx.x & 31;
    if (warp >= BB) return;
    float t = 0.f;
    #pragma unroll
    for (int j = 0; j < 2; ++j) {
        int cidx = lane + j*32;
        float f2 = g_z2[warp*D2 + cidx] * g_a2[cidx] + g_d2[cidx];
        t += f2 * Wp[cidx];
    }
    #pragma unroll
    for (int o = 16; o; o >>= 1) t += __shfl_down_sync(0xffffffffu, t, o);
    if (lane == 0) out_pred[warp] = 1.0f / (1.0f + expf(-(t + bp[0])));
}

// ---------------- launch ------------------------------------------------------------
extern "C" void kernel_launch(void* const* d_in, const int* in_sizes, int n_in,
                              void* d_out, int out_size) {
    const int*   nodes_u     = (const int*)  d_in[0];
    const int*   nodes_v     = (const int*)  d_in[1];
    const int*   nodes_d     = (const int*)  d_in[2];
    const int*   inter_items = (const int*)  d_in[3];
    const int*   top_n       = (const int*)  d_in[4];
    const float* protos      = (const float*)d_in[5];
    const float* pre_text    = (const float*)d_in[6];
    const float* pre_visual  = (const float*)d_in[7];
    const float* Wt          = (const float*)d_in[8];
    const float* bt          = (const float*)d_in[9];
    const float* Wv          = (const float*)d_in[10];
    const float* bv          = (const float*)d_in[11];
    const float* up          = (const float*)d_in[12];
    const float* ip          = (const float*)d_in[13];
    const float* dp          = (const float*)d_in[14];
    const float* W1          = (const float*)d_in[15];
    const float* b1          = (const float*)d_in[16];
    const float* g1          = (const float*)d_in[17];
    const float* be1         = (const float*)d_in[18];
    const float* W2          = (const float*)d_in[19];
    const float* b2          = (const float*)d_in[20];
    const float* g2          = (const float*)d_in[21];
    const float* be2         = (const float*)d_in[22];
    const float* Wp          = (const float*)d_in[23];
    const float* bp          = (const float*)d_in[24];

    float* out      = (float*)d_out;
    float* out_pred = out;
    float* out_pu   = out + BB;
    float* out_hu   = out + BB + BB*DD;
    float* out_pd   = out + BB + 2*BB*DD;

    k_prep<<<296, 256>>>(Wt, Wv, W1, W2, protos);
    k_cb<<<DD, 256>>>(Wt, Wv, bt, bv);
    k_mask<<<BB, 128>>>(nodes_u, nodes_d, inter_items, top_n, up, dp, out_pu, out_pd);
    k_e<<<BB/ESG, 256>>>(nodes_v, pre_text, pre_visual, ip);
    k_hu<<<BB/ESG, 256>>>(nodes_d, dp, out_hu);
    k_z1<<<BB/ESG, 256>>>(b1);
    k_m1<<<1, 128>>>(g1, be1);
    k_z2<<<BB/ESG, 128>>>(b2);
    k_m2<<<1, 64>>>(g2, be2);
    k_pred<<<BB/8, 256>>>(Wp, bp, out_pred);
}

// round 4
// speedup vs baseline: 1.8785x; 1.5547x over previous
#include <cuda_runtime.h>
#include <cstdint>

// Problem constants
#define BB    4096
#define DD    128
#define HIST  50
#define TOPN  4
#define PROTO 1024
#define ITEMS 100000
#define KTOT  1152      // 384 text + 768 visual
#define K1    256       // MLP layer1 input
#define D2    64        // MLP layer2 output
#define ESB   32        // samples per big-GEMM block
#define ESG   16        // samples per z2 block
#define CH    32        // K-floats per chunk
#define XPAD  4         // X row padding (floats) to break bank conflicts

typedef unsigned long long ull;

// ---------------- scratch (__device__ globals; no allocation allowed) ----------------
__device__ float2 g_WT2[(KTOT/2)*DD];   // [k2][c] pairs of transposed [Wt|Wv]
__device__ float2 g_PT2[(PROTO/2)*DD];  // [k2][c] pairs of transposed prototypes
__device__ float2 g_W1T2[(K1/2)*DD];
__device__ float2 g_W2T2[(DD/2)*D2];
__device__ float  g_cb[DD];             // bt·Wt_row + bv·Wv_row
__device__ float  g_mask[BB*PROTO];     // 0/1 presence mask (16MB)
__device__ float  g_cinv[BB];           // 1/unique-count
__device__ float  g_IF[BB*K1];          // inter_feat
__device__ float  g_z1[BB*DD];
__device__ float  g_z2[BB*D2];
__device__ float  g_s1[DD], g_q1[DD], g_a1[DD], g_d1[DD];
__device__ float  g_s2[D2], g_q2[D2], g_a2[D2], g_d2[D2];

__device__ __forceinline__ void ffma2(ull &acc, ull a, ull b) {
    asm("fma.rn.f32x2 %0, %1, %2, %0;" : "+l"(acc) : "l"(a), "l"(b));
}
__device__ __forceinline__ float sum2(ull v) {
    return __uint_as_float((unsigned)v) + __uint_as_float((unsigned)(v >> 32));
}
__device__ __forceinline__ void cpa16(void* dst, const void* src) {
    unsigned d = (unsigned)__cvta_generic_to_shared(dst);
    asm volatile("cp.async.cg.shared.global [%0], [%1], 16;" :: "r"(d), "l"(src));
}
__device__ __forceinline__ void cpa_commit() { asm volatile("cp.async.commit_group;"); }
__device__ __forceinline__ void cpa_wait2() { asm volatile("cp.async.wait_group 2;"); }
__device__ __forceinline__ void cpa_wait1() { asm volatile("cp.async.wait_group 1;"); }
__device__ __forceinline__ void cpa_wait0() { asm volatile("cp.async.wait_group 0;"); }

// ---------------- prep: transpose weights into k-pair float2 layout + zero stats ----
__global__ void k_prep(const float* __restrict__ Wt, const float* __restrict__ Wv,
                       const float* __restrict__ W1, const float* __restrict__ W2,
                       const float* __restrict__ protos) {
    const int n_wt = (KTOT/2)*DD;       // 73728
    const int n_pt = (PROTO/2)*DD;      // 65536
    const int n_w1 = (K1/2)*DD;         // 16384
    const int n_w2 = (DD/2)*D2;         // 4096
    const int n_z  = 2*DD + 2*D2;
    int total = n_wt + n_pt + n_w1 + n_w2 + n_z;
    for (int i = blockIdx.x*blockDim.x + threadIdx.x; i < total; i += gridDim.x*blockDim.x) {
        if (i < n_wt) {
            int k2 = i / DD, c = i % DD;
            int ka = 2*k2, kb = ka + 1;
            float a = (ka < 384) ? Wt[c*384 + ka] : Wv[c*768 + (ka-384)];
            float b = (kb < 384) ? Wt[c*384 + kb] : Wv[c*768 + (kb-384)];
            g_WT2[i] = make_float2(a, b);
        } else if (i < n_wt + n_pt) {
            int j = i - n_wt; int k2 = j / DD, c = j % DD;
            g_PT2[j] = make_float2(protos[(2*k2)*DD + c], protos[(2*k2+1)*DD + c]);
        } else if (i < n_wt + n_pt + n_w1) {
            int j = i - n_wt - n_pt; int k2 = j / DD, c = j % DD;
            g_W1T2[j] = make_float2(W1[c*K1 + 2*k2], W1[c*K1 + 2*k2 + 1]);
        } else if (i < n_wt + n_pt + n_w1 + n_w2) {
            int j = i - n_wt - n_pt - n_w1; int k2 = j / D2, c = j % D2;
            g_W2T2[j] = make_float2(W2[c*DD + 2*k2], W2[c*DD + 2*k2 + 1]);
        } else {
            int j = i - n_wt - n_pt - n_w1 - n_w2;
            if (j < DD)            g_s1[j] = 0.f;
            else if (j < 2*DD)     g_q1[j-DD] = 0.f;
            else if (j < 2*DD+D2)  g_s2[j-2*DD] = 0.f;
            else                   g_q2[j-2*DD-D2] = 0.f;
        }
    }
}

// cb[c] = bt·Wt[c,:] + bv·Wv[c,:]
__global__ void k_cb(const float* __restrict__ Wt, const float* __restrict__ Wv,
                     const float* __restrict__ bt, const float* __restrict__ bv) {
    int c = blockIdx.x, t = threadIdx.x;
    float s = 0.f;
    for (int k = t; k < 384; k += 256) s += bt[k] * Wt[c*384 + k];
    for (int k = t; k < 768; k += 256) s += bv[k] * Wv[c*768 + k];
    __shared__ float red[256];
    red[t] = s; __syncthreads();
    for (int o = 128; o; o >>= 1) { if (t < o) red[t] += red[t+o]; __syncthreads(); }
    if (t == 0) g_cb[c] = red[0];
}

// ---------------- mask build: bitmask -> dense float mask + counts + prompt gathers --
__global__ void k_mask(const int* __restrict__ nodes_u, const int* __restrict__ nodes_d,
                       const int* __restrict__ inter_items, const int* __restrict__ top_n,
                       const float* __restrict__ up, const float* __restrict__ dp,
                       float* __restrict__ out_pu, float* __restrict__ out_pd) {
    __shared__ unsigned bm[PROTO/32];
    int i = blockIdx.x, tid = threadIdx.x;
    if (tid < 32) bm[tid] = 0u;
    __syncthreads();
    for (int j = tid; j < HIST*8; j += 128) {
        int h = j >> 3, r = j & 7;
        int item = inter_items[i*HIST + h];
        int p = (r < 4) ? top_n[item*TOPN + r] : top_n[(item + ITEMS)*TOPN + (r - 4)];
        atomicOr(&bm[p >> 5], 1u << (p & 31));
    }
    __syncthreads();
    if (tid < 32) {
        unsigned c = __popc(bm[tid]);
        #pragma unroll
        for (int o = 16; o; o >>= 1) c += __shfl_down_sync(0xffffffffu, c, o);
        if (tid == 0) g_cinv[i] = 1.0f / (float)c;
    }
    unsigned w = bm[tid >> 2];
    int sh = (tid & 3) * 8;
    float4 a, b;
    a.x = (w >> (sh+0)) & 1 ? 1.f : 0.f;  a.y = (w >> (sh+1)) & 1 ? 1.f : 0.f;
    a.z = (w >> (sh+2)) & 1 ? 1.f : 0.f;  a.w = (w >> (sh+3)) & 1 ? 1.f : 0.f;
    b.x = (w >> (sh+4)) & 1 ? 1.f : 0.f;  b.y = (w >> (sh+5)) & 1 ? 1.f : 0.f;
    b.z = (w >> (sh+6)) & 1 ? 1.f : 0.f;  b.w = (w >> (sh+7)) & 1 ? 1.f : 0.f;
    float4* mrow = (float4*)&g_mask[(size_t)i*PROTO + tid*8];
    mrow[0] = a; mrow[1] = b;
    out_pu[i*DD + tid] = up[nodes_u[i]*DD + tid];
    out_pd[i*DD + tid] = dp[nodes_d[i]*DD + tid];
}

// ===================================================================================
// Big-GEMM tile (256 threads, 32 samples, grid=128, 3-stage cp.async pipeline):
//   warp w in [0,8): col-groups; lane: sg = lane>>3 (sample class), cgl = lane&7
//   cg = w*8+cgl in [0,64): cols 2cg,2cg+1 ; thread samples: i*4+sg, i in [0,8)
//   W chunk smem: [16 k2][64 cg] x 16B = 16KB x3 ; X chunk: [32 samp][36] x4B x3
//   X row stride 144B => the 4 distinct X lines per LDS.128 hit different banks.
// ===================================================================================
#define GEMM_CORE(Wb_, Xb_, bsel)                                              \
    _Pragma("unroll")                                                          \
    for (int p2 = 0; p2 < 8; ++p2) {                                           \
        ulonglong2 w0 = Wb_[bsel][(2*p2)*64 + cg];                             \
        ulonglong2 w1 = Wb_[bsel][(2*p2+1)*64 + cg];                           \
        _Pragma("unroll")                                                      \
        for (int i = 0; i < 8; ++i) {                                          \
            ulonglong2 x = *(const ulonglong2*)&Xb_[bsel][i*4 + sg][4*p2];     \
            ffma2(acc[i][0], w0.x, x.x);                                       \
            ffma2(acc[i][1], w0.y, x.x);                                       \
            ffma2(acc[i][0], w1.x, x.y);                                       \
            ffma2(acc[i][1], w1.y, x.y);                                       \
        }                                                                      \
    }

#define PIPE_WAIT(ch_, nch_)                                                   \
    if ((ch_) + 2 < (nch_)) cpa_wait2();                                       \
    else if ((ch_) + 1 < (nch_)) cpa_wait1();                                  \
    else cpa_wait0();

// ---------------- h_u GEMM: h_u = (mask @ protos)*cinv ; IF[:,0:128] = h_u + p_d ----
__global__ void __launch_bounds__(256) k_hu(const int* __restrict__ nodes_d,
                                            const float* __restrict__ dp,
                                            float* __restrict__ out_hu) {
    __shared__ __align__(16) ulonglong2 Wb[3][16*64];
    __shared__ __align__(16) float Xb[3][ESB][CH+XPAD];
    int blk = blockIdx.x, tid = threadIdx.x;
    int w = tid >> 5, lane = tid & 31;
    int sg = lane >> 3, cgl = lane & 7, cg = w*8 + cgl;
    int c0 = cg*2;
    int xs = tid >> 3, xj = tid & 7;

    auto stage = [&](int ch, int b) {
        const float4* wsrc = (const float4*)(g_PT2 + (ch*(CH/2))*DD);
        const float4* wdst = (const float4*)Wb[b];
        #pragma unroll
        for (int i = 0; i < 4; ++i)
            cpa16((void*)(wdst + tid*4 + i), wsrc + tid*4 + i);
        cpa16(&Xb[b][xs][xj*4],
              &g_mask[(size_t)(blk*ESB + xs)*PROTO + ch*CH + xj*4]);
        cpa_commit();
    };

    ull acc[8][2];
    #pragma unroll
    for (int i = 0; i < 8; ++i) { acc[i][0] = 0ull; acc[i][1] = 0ull; }

    const int NCH = PROTO/CH;   // 32
    stage(0, 0); stage(1, 1);
    #pragma unroll 1
    for (int ch = 0; ch < NCH; ++ch) {
        __syncthreads();                       // compute(ch-1) done by all
        if (ch + 2 < NCH) stage(ch + 2, (ch + 2) % 3);
        PIPE_WAIT(ch, NCH);
        __syncthreads();                       // stage(ch) visible to all
        GEMM_CORE(Wb, Xb, ch % 3);
    }
    #pragma unroll
    for (int i = 0; i < 8; ++i) {
        int s = blk*ESB + i*4 + sg;
        float inv = g_cinv[s];
        int nd = nodes_d[s];
        float h0 = sum2(acc[i][0]) * inv;
        float h1 = sum2(acc[i][1]) * inv;
        *(float2*)&out_hu[s*DD + c0] = make_float2(h0, h1);
        float2 pd = *(const float2*)&dp[nd*DD + c0];
        *(float2*)&g_IF[s*K1 + c0] = make_float2(h0 + pd.x, h1 + pd.y);
    }
}

// ---------------- e_i_hat GEMM: (x-b)@[Wt|Wv]^T + item_prompt -> IF[:,128:256] ------
__global__ void __launch_bounds__(256) k_e(
        const int* __restrict__ nodes_v, const float* __restrict__ pre_text,
        const float* __restrict__ pre_visual, const float* __restrict__ ip) {
    __shared__ int svs[ESB];
    __shared__ __align__(16) ulonglong2 Wb[3][16*64];
    __shared__ __align__(16) float Xb[3][ESB][CH+XPAD];
    int blk = blockIdx.x, tid = threadIdx.x;
    int w = tid >> 5, lane = tid & 31;
    int sg = lane >> 3, cgl = lane & 7, cg = w*8 + cgl;
    int c0 = cg*2;
    if (tid < ESB) svs[tid] = nodes_v[blk*ESB + tid];
    __syncthreads();
    int xs = tid >> 3, xj = tid & 7;
    int xrow = svs[xs];

    auto stage = [&](int ch, int b) {
        int k0 = ch * CH;
        const float4* wsrc = (const float4*)(g_WT2 + (k0 >> 1)*DD);
        const float4* wdst = (const float4*)Wb[b];
        #pragma unroll
        for (int i = 0; i < 4; ++i)
            cpa16((void*)(wdst + tid*4 + i), wsrc + tid*4 + i);
        const float* src = (k0 < 384) ? (pre_text + (size_t)xrow*384 + k0)
                                      : (pre_visual + (size_t)xrow*768 + (k0 - 384));
        cpa16(&Xb[b][xs][xj*4], src + xj*4);
        cpa_commit();
    };

    ull acc[8][2];
    #pragma unroll
    for (int i = 0; i < 8; ++i) { acc[i][0] = 0ull; acc[i][1] = 0ull; }

    const int NCH = KTOT/CH;    // 36
    stage(0, 0); stage(1, 1);
    #pragma unroll 1
    for (int ch = 0; ch < NCH; ++ch) {
        __syncthreads();
        if (ch + 2 < NCH) stage(ch + 2, (ch + 2) % 3);
        PIPE_WAIT(ch, NCH);
        __syncthreads();
        GEMM_CORE(Wb, Xb, ch % 3);
    }
    float2 cbv = *(const float2*)&g_cb[c0];
    #pragma unroll
    for (int i = 0; i < 8; ++i) {
        int sl = i*4 + sg;
        int s = blk*ESB + sl;
        float2 ipv = *(const float2*)&ip[(size_t)svs[sl]*DD + c0];
        float e0 = sum2(acc[i][0]) - cbv.x + ipv.x;
        float e1 = sum2(acc[i][1]) - cbv.y + ipv.y;
        *(float2*)&g_IF[s*K1 + DD + c0] = make_float2(e0, e1);
    }
}

// ---------------- z1 = relu(IF @ W1^T + b1) + partial BN stats ---------------------
__global__ void __launch_bounds__(256) k_z1(const float* __restrict__ b1) {
    __shared__ __align__(16) ulonglong2 Wb[3][16*64];
    __shared__ __align__(16) float Xb[3][ESB][CH+XPAD];
    int blk = blockIdx.x, tid = threadIdx.x;
    int w = tid >> 5, lane = tid & 31;
    int sg = lane >> 3, cgl = lane & 7, cg = w*8 + cgl;
    int c0 = cg*2;
    int xs = tid >> 3, xj = tid & 7;

    auto stage = [&](int ch, int b) {
        const float4* wsrc = (const float4*)(g_W1T2 + (ch*(CH/2))*DD);
        const float4* wdst = (const float4*)Wb[b];
        #pragma unroll
        for (int i = 0; i < 4; ++i)
            cpa16((void*)(wdst + tid*4 + i), wsrc + tid*4 + i);
        cpa16(&Xb[b][xs][xj*4], &g_IF[(blk*ESB + xs)*K1 + ch*CH + xj*4]);
        cpa_commit();
    };

    ull acc[8][2];
    #pragma unroll
    for (int i = 0; i < 8; ++i) { acc[i][0] = 0ull; acc[i][1] = 0ull; }

    const int NCH = K1/CH;  // 8
    stage(0, 0); stage(1, 1);
    #pragma unroll 1
    for (int ch = 0; ch < NCH; ++ch) {
        __syncthreads();
        if (ch + 2 < NCH) stage(ch + 2, (ch + 2) % 3);
        PIPE_WAIT(ch, NCH);
        __syncthreads();
        GEMM_CORE(Wb, Xb, ch % 3);
    }
    float2 bb = *(const float2*)&b1[c0];
    float s0 = 0.f, s1 = 0.f, q0 = 0.f, q1 = 0.f;
    #pragma unroll
    for (int i = 0; i < 8; ++i) {
        int s = blk*ESB + i*4 + sg;
        float z0 = sum2(acc[i][0]) + bb.x;  z0 = z0 > 0.f ? z0 : 0.f;
        float z1v = sum2(acc[i][1]) + bb.y; z1v = z1v > 0.f ? z1v : 0.f;
        *(float2*)&g_z1[s*DD + c0] = make_float2(z0, z1v);
        s0 += z0; s1 += z1v; q0 += z0*z0; q1 += z1v*z1v;
    }
    #pragma unroll
    for (int o = 8; o <= 16; o <<= 1) {
        s0 += __shfl_xor_sync(0xffffffffu, s0, o);
        s1 += __shfl_xor_sync(0xffffffffu, s1, o);
        q0 += __shfl_xor_sync(0xffffffffu, q0, o);
        q1 += __shfl_xor_sync(0xffffffffu, q1, o);
    }
    if (sg == 0) {
        atomicAdd(&g_s1[c0], s0);   atomicAdd(&g_s1[c0+1], s1);
        atomicAdd(&g_q1[c0], q0);   atomicAdd(&g_q1[c0+1], q1);
    }
}

__global__ void k_m1(const float* __restrict__ g1, const float* __restrict__ be1) {
    int c = threadIdx.x;  // 128
    float m = g_s1[c] * (1.0f/BB);
    float v = g_q1[c] * (1.0f/BB) - m*m;
    float r = rsqrtf(v + 1e-5f);
    float a = g1[c] * r;
    g_a1[c] = a;
    g_d1[c] = be1[c] - m*a;
}

// ---------------- z2 = relu(BN(z1) @ W2^T + b2) + partial BN stats -----------------
__global__ void __launch_bounds__(128) k_z2(const float* __restrict__ b2) {
    __shared__ __align__(16) float2 W2s[(DD/2)*D2];  // 32KB
    __shared__ __align__(16) float X[ESG][DD];       // 8KB
    __shared__ float A1[DD], D1[DD];
    int blk = blockIdx.x, tid = threadIdx.x;
    int c = tid & 63, h = tid >> 6;
    if (tid < DD) { A1[tid] = g_a1[tid]; D1[tid] = g_d1[tid]; }
    {
        const float4* src = (const float4*)g_W2T2;
        float4* dst = (float4*)W2s;
        #pragma unroll
        for (int i = 0; i < 16; ++i)
            cpa16(dst + tid + i*128, src + tid + i*128);
        cpa_commit();
    }
    __syncthreads();
    for (int l = tid; l < ESG*DD; l += 128) {
        int s = l >> 7, kk = l & 127;
        X[s][kk] = g_z1[(blk*ESG + s)*DD + kk] * A1[kk] + D1[kk];
    }
    cpa_wait0();
    __syncthreads();
    ull acc[8];
    #pragma unroll
    for (int i = 0; i < 8; ++i) acc[i] = 0ull;
    #pragma unroll 8
    for (int p = 0; p < DD/2; ++p) {
        ull wv = *(const ull*)&W2s[p*D2 + c];
        #pragma unroll
        for (int i = 0; i < 8; ++i) {
            ull x = *(const ull*)&X[h*8 + i][2*p];
            ffma2(acc[i], wv, x);
        }
    }
    float bb = b2[c];
    float lsum = 0.f, lss = 0.f;
    #pragma unroll
    for (int i = 0; i < 8; ++i) {
        float z = sum2(acc[i]) + bb;
        z = z > 0.f ? z : 0.f;
        g_z2[(blk*ESG + h*8 + i)*D2 + c] = z;
        lsum += z; lss += z*z;
    }
    atomicAdd(&g_s2[c], lsum);
    atomicAdd(&g_q2[c], lss);
}

__global__ void k_m2(const float* __restrict__ g2, const float* __restrict__ be2) {
    int c = threadIdx.x;  // 64
    float m = g_s2[c] * (1.0f/BB);
    float v = g_q2[c] * (1.0f/BB) - m*m;
    float r = rsqrtf(v + 1e-5f);
    float a = g2[c] * r;
    g_a2[c] = a;
    g_d2[c] = be2[c] - m*a;
}

// ---------------- pred = sigmoid(BN(z2) @ Wp^T + bp) -------------------------------
__global__ void k_pred(const float* __restrict__ Wp, const float* __restrict__ bp,
                       float* __restrict__ out_pred) {
    int warp = (blockIdx.x*blockDim.x + threadIdx.x) >> 5;
    int lane = threadIdx.x & 31;
    if (warp >= BB) return;
    float t = 0.f;
    #pragma unroll
    for (int j = 0; j < 2; ++j) {
        int cidx = lane + j*32;
        float f2 = g_z2[warp*D2 + cidx] * g_a2[cidx] + g_d2[cidx];
        t += f2 * Wp[cidx];
    }
    #pragma unroll
    for (int o = 16; o; o >>= 1) t += __shfl_down_sync(0xffffffffu, t, o);
    if (lane == 0) out_pred[warp] = 1.0f / (1.0f + expf(-(t + bp[0])));
}

// ---------------- launch ------------------------------------------------------------
extern "C" void kernel_launch(void* const* d_in, const int* in_sizes, int n_in,
                              void* d_out, int out_size) {
    const int*   nodes_u     = (const int*)  d_in[0];
    const int*   nodes_v     = (const int*)  d_in[1];
    const int*   nodes_d     = (const int*)  d_in[2];
    const int*   inter_items = (const int*)  d_in[3];
    const int*   top_n       = (const int*)  d_in[4];
    const float* protos      = (const float*)d_in[5];
    const float* pre_text    = (const float*)d_in[6];
    const float* pre_visual  = (const float*)d_in[7];
    const float* Wt          = (const float*)d_in[8];
    const float* bt          = (const float*)d_in[9];
    const float* Wv          = (const float*)d_in[10];
    const float* bv          = (const float*)d_in[11];
    const float* up          = (const float*)d_in[12];
    const float* ip          = (const float*)d_in[13];
    const float* dp          = (const float*)d_in[14];
    const float* W1          = (const float*)d_in[15];
    const float* b1          = (const float*)d_in[16];
    const float* g1          = (const float*)d_in[17];
    const float* be1         = (const float*)d_in[18];
    const float* W2          = (const float*)d_in[19];
    const float* b2          = (const float*)d_in[20];
    const float* g2          = (const float*)d_in[21];
    const float* be2         = (const float*)d_in[22];
    const float* Wp          = (const float*)d_in[23];
    const float* bp          = (const float*)d_in[24];

    float* out      = (float*)d_out;
    float* out_pred = out;
    float* out_pu   = out + BB;
    float* out_hu   = out + BB + BB*DD;
    float* out_pd   = out + BB + 2*BB*DD;

    k_prep<<<296, 256>>>(Wt, Wv, W1, W2, protos);
    k_cb<<<DD, 256>>>(Wt, Wv, bt, bv);
    k_mask<<<BB, 128>>>(nodes_u, nodes_d, inter_items, top_n, up, dp, out_pu, out_pd);
    k_e<<<BB/ESB, 256>>>(nodes_v, pre_text, pre_visual, ip);
    k_hu<<<BB/ESB, 256>>>(nodes_d, dp, out_hu);
    k_z1<<<BB/ESB, 256>>>(b1);
    k_m1<<<1, 128>>>(g1, be1);
    k_z2<<<BB/ESG, 128>>>(b2);
    k_m2<<<1, 64>>>(g2, be2);
    k_pred<<<BB/8, 256>>>(Wp, bp, out_pred);
}